// round 10
// baseline (speedup 1.0000x reference)
#include <cuda_runtime.h>
#include <math_constants.h>

#define Bsz 2048
#define Dd 16
#define Ff 512
#define LOG2E_F 1.4426950408889634f
#define LN2_F 0.6931471805599453f
#define LOG2PI_F 1.8378770664093453f

#define NPAIR 256            // pairwise blocks: 128 row-groups x 2 j-halves
#define NRECON 64            // recon blocks
#define NGRID (NPAIR + NRECON)

typedef unsigned long long ull;

// Coefficient store: segment s = dp*3 + type (dp=dim-pair 0..7, type a/b/c),
// each segment is float2[2048] over j: float2[j] = {coef_{2dp}[j], coef_{2dp+1}[j]}
__device__ float g_pk2f[24 * 2048 * 2];   // 393 KB
__device__ float g_arr0[Bsz];             // log q(z|x) - log p(z)
__device__ float g_ph[2][Bsz * 20];       // per-half partials: 16 dim sums + srow (pad 20)
__device__ float g_comb[Bsz];             // arr0 + 3*ln2*(lg2 srow - sum lg2 s_d)
__device__ float g_part[NRECON];          // recon partials
__device__ unsigned g_rgc[128];           // per-rowgroup half counters
__device__ unsigned g_count;              // last-block-done counter

__device__ __forceinline__ float ex2f(float x) {
    float y; asm("ex2.approx.ftz.f32 %0, %1;" : "=f"(y) : "f"(x)); return y;
}
__device__ __forceinline__ float lg2f_(float x) {
    float y; asm("lg2.approx.f32 %0, %1;" : "=f"(y) : "f"(x)); return y;
}
__device__ __forceinline__ ull fma2_(ull a, ull b, ull c) {
    ull d; asm("fma.rn.f32x2 %0, %1, %2, %3;" : "=l"(d) : "l"(a), "l"(b), "l"(c)); return d;
}
__device__ __forceinline__ ull add2_(ull a, ull b) {
    ull d; asm("add.rn.f32x2 %0, %1, %2;" : "=l"(d) : "l"(a), "l"(b)); return d;
}
__device__ __forceinline__ void unpk(ull v, float& lo, float& hi) {
    asm("mov.b64 {%0, %1}, %2;" : "=f"(lo), "=f"(hi) : "l"(v));
}
__device__ __forceinline__ ull pk2(float lo, float hi) {
    ull v; asm("mov.b64 %0, {%1, %2};" : "=l"(v) : "f"(lo), "f"(hi)); return v;
}
__device__ __forceinline__ void cpa16(unsigned d, const void* s) {
    asm volatile("cp.async.cg.shared.global [%0], [%1], 16;" :: "r"(d), "l"(s));
}

// ---------------------------------------------------------------------------
// K_prep: blocks [0,128): coefficients (j-major, dim-pair packed, log2 domain,
//         j=0/1 importance-weight deltas folded into c).
//         blocks [128,136): per-i  log q(z|x) - log p(z).
// Also resets the counters for k_main.
// ---------------------------------------------------------------------------
__global__ void k_prep(const float* __restrict__ mu, const float* __restrict__ lv,
                       const float* __restrict__ z, const int* __restrict__ nds) {
    int b = blockIdx.x;
    if (b == 0) {
        if (threadIdx.x == 0) g_count = 0u;
        if (threadIdx.x < 128) g_rgc[threadIdx.x] = 0u;
    }
    if (b < 128) {
        int idx = b * 256 + threadIdx.x;          // exactly 32768 = Bsz*Dd
        int j = idx >> 4, d = idx & 15;
        float m = mu[idx], v = lv[idx];
        float a = -0.5f * LOG2E_F * ex2f(-v * LOG2E_F);
        float off = -0.5f * LOG2E_F * (v + LOG2PI_F);
        float bb = -2.0f * a * m;
        float c = fmaf(a * m, m, off);
        if (j < 2) {
            float Nf = (float)(*nds);
            float dL0 = lg2f_(2047.0f / Nf);
            float dL1 = lg2f_((Nf - 2047.0f) / Nf);
            c += (j == 0) ? dL0 : dL1;
        }
        int dp = d >> 1, h = d & 1;
        int e = j * 2 + h;
        g_pk2f[(dp * 3 + 0) * 4096 + e] = a;
        g_pk2f[(dp * 3 + 1) * 4096 + e] = bb;
        g_pk2f[(dp * 3 + 2) * 4096 + e] = c;
    } else {
        int i = (b - 128) * 256 + threadIdx.x;    // exactly 2048
        float acc = 0.f, sz2 = 0.f;
#pragma unroll
        for (int d = 0; d < Dd; d++) {
            float zd = z[i * Dd + d];
            float md = mu[i * Dd + d];
            float vd = lv[i * Dd + d];
            float t = zd - md;
            acc += -0.5f * (t * t * ex2f(-vd * LOG2E_F) + vd + LOG2PI_F);
            sz2 = fmaf(zd, zd, sz2);
        }
        float lprior = -0.5f * (sz2 * 0.36787944117144233f + 16.0f * (1.0f + LOG2PI_F));
        g_arr0[i] = acc - lprior;
    }
}

// ---------------------------------------------------------------------------
// K_main: 256 pairwise blocks (rowgroup x j-half) + 64 recon blocks, 256 thr,
// 2 CTAs/SM. Pairwise: 8 warps x 2 rows; 16 j-tiles of 64 j staged via
// cp.async double-buffer; plain exp2-accumulate; j=0/1 corrections in half 0;
// halves merged by the per-rowgroup second finisher (deterministic).
// LAST block overall (atomic counter, fixed-order reduce) writes out[0].
// ---------------------------------------------------------------------------
__global__ void __launch_bounds__(256, 2) k_main(const float* __restrict__ z,
                                                 const int* __restrict__ nds,
                                                 const float* __restrict__ x,
                                                 const float* __restrict__ rec,
                                                 float* __restrict__ out) {
    __shared__ float4 sbuf[2][768];               // 2 x 12 KB tiles
    __shared__ float sred[256];
    __shared__ unsigned s_tmp;
    const int tid = threadIdx.x;
    const int lane = tid & 31;

    if (blockIdx.x < NPAIR) {
        // ---------------- pairwise block ----------------
        const int half = blockIdx.x >> 7;         // 0 or 1 (j-half)
        const int rg = blockIdx.x & 127;          // row-group (16 rows)
        const int w = tid >> 5;                   // 0..7
        const int i0 = rg * 16 + 2 * w, i1 = i0 + 1;

        ull zp0[8], zp1[8];
        {
            const float4* zq = (const float4*)(z + (size_t)i0 * Dd);
#pragma unroll
            for (int k = 0; k < 4; k++) {
                float4 v = zq[k];
                zp0[2 * k] = pk2(v.x, v.y); zp0[2 * k + 1] = pk2(v.z, v.w);
            }
            const float4* zq1 = (const float4*)(z + (size_t)i1 * Dd);
#pragma unroll
            for (int k = 0; k < 4; k++) {
                float4 v = zq1[k];
                zp1[2 * k] = pk2(v.x, v.y); zp1[2 * k + 1] = pk2(v.z, v.w);
            }
        }

        float s0[16], s1[16], srow0 = 0.f, srow1 = 0.f;
#pragma unroll
        for (int d = 0; d < 16; d++) { s0[d] = 0.f; s1[d] = 0.f; }

        // cp.async bases: chunk k covers element e=tid+k*256 -> seg s=e>>5, q=e&31
        const char* srcb[3];
        unsigned dstb[3];
        {
            unsigned sm0 = (unsigned)__cvta_generic_to_shared(&sbuf[0][0]);
#pragma unroll
            for (int k = 0; k < 3; k++) {
                int e = tid + k * 256; int s = e >> 5, q = e & 31;
                srcb[k] = (const char*)g_pk2f + ((size_t)(s * 1024 + q)) * 16
                        + (size_t)half * 16 * 512;
                dstb[k] = sm0 + (unsigned)(s * 32 + q) * 16u;
            }
        }
        // prologue: stage local tile 0
#pragma unroll
        for (int k = 0; k < 3; k++) cpa16(dstb[k], srcb[k]);
        asm volatile("cp.async.commit_group;");

#pragma unroll 1
        for (int t = 0; t < 16; t++) {
            if (t < 15) {
                unsigned boff = ((t + 1) & 1) * 12288u;
#pragma unroll
                for (int k = 0; k < 3; k++)
                    cpa16(dstb[k] + boff, srcb[k] + (size_t)(t + 1) * 512);
                asm volatile("cp.async.commit_group;");
                asm volatile("cp.async.wait_group 1;");
            } else {
                asm volatile("cp.async.wait_group 0;");
            }
            __syncthreads();

            const ulonglong2* sb2 = (const ulonglong2*)sbuf[t & 1];
            ull SR00 = 0ull, SR01 = 0ull, SR10 = 0ull, SR11 = 0ull;

#pragma unroll
            for (int dp = 0; dp < 8; dp++) {
                ulonglong2 A = sb2[(dp * 3 + 0) * 32 + lane];
                ulonglong2 B = sb2[(dp * 3 + 1) * 32 + lane];
                ulonglong2 C = sb2[(dp * 3 + 2) * 32 + lane];
                float l, h;
                ull u = fma2_(zp0[dp], fma2_(zp0[dp], A.x, B.x), C.x);
                unpk(u, l, h); s0[2 * dp] += ex2f(l); s0[2 * dp + 1] += ex2f(h);
                SR00 = add2_(SR00, u);
                u = fma2_(zp0[dp], fma2_(zp0[dp], A.y, B.y), C.y);
                unpk(u, l, h); s0[2 * dp] += ex2f(l); s0[2 * dp + 1] += ex2f(h);
                SR01 = add2_(SR01, u);
                u = fma2_(zp1[dp], fma2_(zp1[dp], A.x, B.x), C.x);
                unpk(u, l, h); s1[2 * dp] += ex2f(l); s1[2 * dp + 1] += ex2f(h);
                SR10 = add2_(SR10, u);
                u = fma2_(zp1[dp], fma2_(zp1[dp], A.y, B.y), C.y);
                unpk(u, l, h); s1[2 * dp] += ex2f(l); s1[2 * dp + 1] += ex2f(h);
                SR11 = add2_(SR11, u);
            }
            {
                float l, h;
                unpk(SR00, l, h); srow0 += ex2f(l + h);
                unpk(SR01, l, h); srow0 += ex2f(l + h);
                unpk(SR10, l, h); srow1 += ex2f(l + h);
                unpk(SR11, l, h); srow1 += ex2f(l + h);
            }
            __syncthreads();   // all done reading buf[t&1] before its re-fill
        }

        // ---- post-loop exact corrections: j=0/1 live in half 0, lane 0 ----
        if (half == 0 && lane == 0) {
            const ulonglong2* pk = (const ulonglong2*)g_pk2f;
            float Nf = (float)(*nds);
            float dL0 = lg2f_(2047.0f / Nf);
            float dL1 = lg2f_((Nf - 2047.0f) / Nf);
            float S0_0 = 0.f, S1_0 = 0.f, S0_1 = 0.f, S1_1 = 0.f;
#pragma unroll
            for (int dp = 0; dp < 8; dp++) {
                ulonglong2 A = pk[(dp * 3 + 0) * 1024];
                ulonglong2 B = pk[(dp * 3 + 1) * 1024];
                ulonglong2 C = pk[(dp * 3 + 2) * 1024];
                float l, h;
                ull u0 = fma2_(zp0[dp], fma2_(zp0[dp], A.x, B.x), C.x);
                unpk(u0, l, h); S0_0 += l + h;
                ull u1 = fma2_(zp0[dp], fma2_(zp0[dp], A.y, B.y), C.y);
                unpk(u1, l, h); S1_0 += l + h;
                ull v0 = fma2_(zp1[dp], fma2_(zp1[dp], A.x, B.x), C.x);
                unpk(v0, l, h); S0_1 += l + h;
                ull v1 = fma2_(zp1[dp], fma2_(zp1[dp], A.y, B.y), C.y);
                unpk(v1, l, h); S1_1 += l + h;
            }
            // row-sum: loop applied 16*dL_j; true weight is 1*dL_j(row).
            float c00 = (i0 == Bsz - 2) ? (dL1 - 16.f * dL0) : (-15.f * dL0);
            float c01 = -15.f * dL0;                  // odd rows are never B-2
            float c1  = -15.f * dL1;
            srow0 += (ex2f(c00) - 1.f) * ex2f(S0_0) + (ex2f(c1) - 1.f) * ex2f(S1_0);
            srow1 += (ex2f(c01) - 1.f) * ex2f(S0_1) + (ex2f(c1) - 1.f) * ex2f(S1_1);
            // W[B-2, 0] per-dim override (row B-2 is even -> row i0): recompute u
            if (i0 == Bsz - 2) {
                float wfix = ex2f(dL1 - dL0) - 1.f;
#pragma unroll
                for (int dp = 0; dp < 8; dp++) {
                    ulonglong2 A = pk[(dp * 3 + 0) * 1024];
                    ulonglong2 B = pk[(dp * 3 + 1) * 1024];
                    ulonglong2 C = pk[(dp * 3 + 2) * 1024];
                    float l, h;
                    ull u0 = fma2_(zp0[dp], fma2_(zp0[dp], A.x, B.x), C.x);
                    unpk(u0, l, h);
                    s0[2 * dp] += wfix * ex2f(l);
                    s0[2 * dp + 1] += wfix * ex2f(h);
                }
            }
        }

        // ---- plain-sum butterfly ----
#pragma unroll
        for (int off = 16; off > 0; off >>= 1) {
#pragma unroll
            for (int d = 0; d < 16; d++) {
                s0[d] += __shfl_xor_sync(0xffffffffu, s0[d], off);
                s1[d] += __shfl_xor_sync(0xffffffffu, s1[d], off);
            }
            srow0 += __shfl_xor_sync(0xffffffffu, srow0, off);
            srow1 += __shfl_xor_sync(0xffffffffu, srow1, off);
        }

        // ---- write half partials ----
        if (lane == 0) {
            float4* d0 = (float4*)&g_ph[half][i0 * 20];
            d0[0] = make_float4(s0[0], s0[1], s0[2], s0[3]);
            d0[1] = make_float4(s0[4], s0[5], s0[6], s0[7]);
            d0[2] = make_float4(s0[8], s0[9], s0[10], s0[11]);
            d0[3] = make_float4(s0[12], s0[13], s0[14], s0[15]);
            g_ph[half][i0 * 20 + 16] = srow0;
            float4* d1 = (float4*)&g_ph[half][i1 * 20];
            d1[0] = make_float4(s1[0], s1[1], s1[2], s1[3]);
            d1[1] = make_float4(s1[4], s1[5], s1[6], s1[7]);
            d1[2] = make_float4(s1[8], s1[9], s1[10], s1[11]);
            d1[3] = make_float4(s1[12], s1[13], s1[14], s1[15]);
            g_ph[half][i1 * 20 + 16] = srow1;
        }
        __syncthreads();
        if (tid == 0) {
            __threadfence();
            s_tmp = atomicAdd(&g_rgc[rg], 1u);
        }
        __syncthreads();
        if (s_tmp == 1) {            // second finisher merges this rowgroup
            __threadfence();
            if (lane == 0) {
                const float* o0 = &g_ph[1 - half][i0 * 20];
                float acc = 0.f;
#pragma unroll
                for (int d = 0; d < 16; d++) acc += lg2f_(s0[d] + o0[d]);
                g_comb[i0] = g_arr0[i0]
                           + 3.f * LN2_F * (lg2f_(srow0 + o0[16]) - acc);
                const float* o1 = &g_ph[1 - half][i1 * 20];
                acc = 0.f;
#pragma unroll
                for (int d = 0; d < 16; d++) acc += lg2f_(s1[d] + o1[d]);
                g_comb[i1] = g_arr0[i1]
                           + 3.f * LN2_F * (lg2f_(srow1 + o1[16]) - acc);
            }
        }
    } else {
        // ---------------- recon MAE partial ----------------
        const int rb = blockIdx.x - NPAIR;
        float acc = 0.f;
        const float4* x4 = (const float4*)x;
        const float4* r4 = (const float4*)rec;
        const int n4 = (Bsz * Ff) / 4;
        for (int k = rb * 256 + tid; k < n4; k += NRECON * 256) {
            float4 a = x4[k], b = r4[k];
            acc += fabsf(a.x - b.x) + fabsf(a.y - b.y) + fabsf(a.z - b.z) + fabsf(a.w - b.w);
        }
        sred[tid] = acc;
        __syncthreads();
#pragma unroll
        for (int o = 128; o > 0; o >>= 1) {
            if (tid < o) sred[tid] += sred[tid + o];
            __syncthreads();
        }
        if (tid == 0) g_part[rb] = sred[0];
    }

    // ---------------- last-block final combine ----------------
    __threadfence();
    __syncthreads();
    if (tid == 0) s_tmp = atomicAdd(&g_count, 1u);
    __syncthreads();
    if (s_tmp == NGRID - 1) {
        __threadfence();
        // total = recon_mean + mean(comb) + 45*ln(2047)
        float c = 0.f;
#pragma unroll
        for (int k = 0; k < Bsz / 256; k++)
            c += g_comb[tid + k * 256];
        float rp = (tid < NRECON) ? g_part[tid] : 0.f;

        sred[tid] = c;
        __syncthreads();
#pragma unroll
        for (int o = 128; o > 0; o >>= 1) {
            if (tid < o) sred[tid] += sred[tid + o];
            __syncthreads();
        }
        float ctot = sred[0];
        __syncthreads();
        sred[tid] = rp;
        __syncthreads();
#pragma unroll
        for (int o = 128; o > 0; o >>= 1) {
            if (tid < o) sred[tid] += sred[tid + o];
            __syncthreads();
        }
        if (tid == 0)
            out[0] = sred[0] / (float)(Bsz * Ff) + ctot / (float)Bsz
                   + 45.0f * logf(2047.0f);
    }
}

extern "C" void kernel_launch(void* const* d_in, const int* in_sizes, int n_in,
                              void* d_out, int out_size) {
    const float* x   = (const float*)d_in[0];
    const float* rec = (const float*)d_in[1];
    const float* mu  = (const float*)d_in[2];
    const float* lv  = (const float*)d_in[3];
    const float* z   = (const float*)d_in[4];
    const int*   nds = (const int*)d_in[5];
    float* out = (float*)d_out;

    k_prep<<<136, 256>>>(mu, lv, z, nds);
    k_main<<<NGRID, 256>>>(z, nds, x, rec, out);
}

// round 11
// speedup vs baseline: 1.0091x; 1.0091x over previous
#include <cuda_runtime.h>
#include <math_constants.h>

#define Bsz 2048
#define Dd 16
#define Ff 512
#define LOG2E_F 1.4426950408889634f
#define LN2_F 0.6931471805599453f
#define LOG2PI_F 1.8378770664093453f

#define NPAIR 256            // pairwise blocks: 128 row-groups x 2 j-halves
#define NRECON 40            // recon blocks -> total 296 = one full wave (148 SM x 2)
#define NGRID (NPAIR + NRECON)

typedef unsigned long long ull;

// Coefficient store: segment s = dp*3 + type (dp=dim-pair 0..7, type a/b/c),
// each segment is float2[2048] over j: float2[j] = {coef_{2dp}[j], coef_{2dp+1}[j]}
__device__ float g_pk2f[24 * 2048 * 2];   // 393 KB
__device__ float g_arr0[Bsz];             // log q(z|x) - log p(z)
__device__ float g_ph[2][Bsz * 20];       // per-half partials: 16 dim sums + srow (pad 20)
__device__ float g_comb[Bsz];             // arr0 + 3*ln2*(lg2 srow - sum lg2 s_d)
__device__ float g_part[NRECON];          // recon partials
__device__ unsigned g_rgc[128];           // per-rowgroup half counters
__device__ unsigned g_count;              // last-block-done counter

__device__ __forceinline__ float ex2f(float x) {
    float y; asm("ex2.approx.ftz.f32 %0, %1;" : "=f"(y) : "f"(x)); return y;
}
__device__ __forceinline__ float lg2f_(float x) {
    float y; asm("lg2.approx.f32 %0, %1;" : "=f"(y) : "f"(x)); return y;
}
__device__ __forceinline__ ull fma2_(ull a, ull b, ull c) {
    ull d; asm("fma.rn.f32x2 %0, %1, %2, %3;" : "=l"(d) : "l"(a), "l"(b), "l"(c)); return d;
}
__device__ __forceinline__ ull add2_(ull a, ull b) {
    ull d; asm("add.rn.f32x2 %0, %1, %2;" : "=l"(d) : "l"(a), "l"(b)); return d;
}
__device__ __forceinline__ void unpk(ull v, float& lo, float& hi) {
    asm("mov.b64 {%0, %1}, %2;" : "=f"(lo), "=f"(hi) : "l"(v));
}
__device__ __forceinline__ ull pk2(float lo, float hi) {
    ull v; asm("mov.b64 %0, {%1, %2};" : "=l"(v) : "f"(lo), "f"(hi)); return v;
}
__device__ __forceinline__ void cpa16(unsigned d, const void* s) {
    asm volatile("cp.async.cg.shared.global [%0], [%1], 16;" :: "r"(d), "l"(s));
}

// ---------------------------------------------------------------------------
// K_prep: blocks [0,128): coefficients (j-major, dim-pair packed, log2 domain,
//         j=0/1 importance-weight deltas folded into c).
//         blocks [128,136): per-i  log q(z|x) - log p(z).
// Also resets the counters for k_main.
// ---------------------------------------------------------------------------
__global__ void k_prep(const float* __restrict__ mu, const float* __restrict__ lv,
                       const float* __restrict__ z, const int* __restrict__ nds) {
    int b = blockIdx.x;
    if (b == 0) {
        if (threadIdx.x == 0) g_count = 0u;
        if (threadIdx.x < 128) g_rgc[threadIdx.x] = 0u;
    }
    if (b < 128) {
        int idx = b * 256 + threadIdx.x;          // exactly 32768 = Bsz*Dd
        int j = idx >> 4, d = idx & 15;
        float m = mu[idx], v = lv[idx];
        float a = -0.5f * LOG2E_F * ex2f(-v * LOG2E_F);
        float off = -0.5f * LOG2E_F * (v + LOG2PI_F);
        float bb = -2.0f * a * m;
        float c = fmaf(a * m, m, off);
        if (j < 2) {
            float Nf = (float)(*nds);
            float dL0 = lg2f_(2047.0f / Nf);
            float dL1 = lg2f_((Nf - 2047.0f) / Nf);
            c += (j == 0) ? dL0 : dL1;
        }
        int dp = d >> 1, h = d & 1;
        int e = j * 2 + h;
        g_pk2f[(dp * 3 + 0) * 4096 + e] = a;
        g_pk2f[(dp * 3 + 1) * 4096 + e] = bb;
        g_pk2f[(dp * 3 + 2) * 4096 + e] = c;
    } else {
        int i = (b - 128) * 256 + threadIdx.x;    // exactly 2048
        float acc = 0.f, sz2 = 0.f;
#pragma unroll
        for (int d = 0; d < Dd; d++) {
            float zd = z[i * Dd + d];
            float md = mu[i * Dd + d];
            float vd = lv[i * Dd + d];
            float t = zd - md;
            acc += -0.5f * (t * t * ex2f(-vd * LOG2E_F) + vd + LOG2PI_F);
            sz2 = fmaf(zd, zd, sz2);
        }
        float lprior = -0.5f * (sz2 * 0.36787944117144233f + 16.0f * (1.0f + LOG2PI_F));
        g_arr0[i] = acc - lprior;
    }
}

// ---------------------------------------------------------------------------
// K_main: 256 pairwise blocks (rowgroup x j-half) + 40 recon blocks, 256 thr,
// 2 CTAs/SM, exactly one wave. Pairwise: 8 warps x 2 rows; 16 j-tiles of 64 j
// staged via TRIPLE-buffered cp.async with a SINGLE barrier per tile:
//   wait(t); sync; compute(t) from buf[t%3]; fill(t+2) -> buf[(t+2)%3]; commit
// fill(t+2) overwrites the buffer read at t-1; the sync at iter t proves all
// threads completed compute(t-1), so one barrier suffices.
// Halves merged by the per-rowgroup second finisher; last block writes out[0].
// ---------------------------------------------------------------------------
__global__ void __launch_bounds__(256, 2) k_main(const float* __restrict__ z,
                                                 const int* __restrict__ nds,
                                                 const float* __restrict__ x,
                                                 const float* __restrict__ rec,
                                                 float* __restrict__ out) {
    __shared__ float4 sbuf[3][768];               // 3 x 12 KB tiles
    __shared__ float sred[256];
    __shared__ unsigned s_tmp;
    const int tid = threadIdx.x;
    const int lane = tid & 31;

    if (blockIdx.x < NPAIR) {
        // ---------------- pairwise block ----------------
        const int half = blockIdx.x >> 7;         // 0 or 1 (j-half)
        const int rg = blockIdx.x & 127;          // row-group (16 rows)
        const int w = tid >> 5;                   // 0..7
        const int i0 = rg * 16 + 2 * w, i1 = i0 + 1;

        ull zp0[8], zp1[8];
        {
            const float4* zq = (const float4*)(z + (size_t)i0 * Dd);
#pragma unroll
            for (int k = 0; k < 4; k++) {
                float4 v = zq[k];
                zp0[2 * k] = pk2(v.x, v.y); zp0[2 * k + 1] = pk2(v.z, v.w);
            }
            const float4* zq1 = (const float4*)(z + (size_t)i1 * Dd);
#pragma unroll
            for (int k = 0; k < 4; k++) {
                float4 v = zq1[k];
                zp1[2 * k] = pk2(v.x, v.y); zp1[2 * k + 1] = pk2(v.z, v.w);
            }
        }

        float s0[16], s1[16], srow0 = 0.f, srow1 = 0.f;
#pragma unroll
        for (int d = 0; d < 16; d++) { s0[d] = 0.f; s1[d] = 0.f; }

        // cp.async bases: chunk k covers element e=tid+k*256 -> seg s=e>>5, q=e&31
        const char* srcb[3];
        unsigned dstb[3];
        {
            unsigned sm0 = (unsigned)__cvta_generic_to_shared(&sbuf[0][0]);
#pragma unroll
            for (int k = 0; k < 3; k++) {
                int e = tid + k * 256; int s = e >> 5, q = e & 31;
                srcb[k] = (const char*)g_pk2f + ((size_t)(s * 1024 + q)) * 16
                        + (size_t)half * 8192;
                dstb[k] = sm0 + (unsigned)(s * 32 + q) * 16u;
            }
        }
        // prologue: stage tiles 0 and 1
#pragma unroll
        for (int k = 0; k < 3; k++) cpa16(dstb[k], srcb[k]);
        asm volatile("cp.async.commit_group;");
#pragma unroll
        for (int k = 0; k < 3; k++) cpa16(dstb[k] + 12288u, srcb[k] + 512);
        asm volatile("cp.async.commit_group;");

        int rb = 0;   // t % 3
#pragma unroll 1
        for (int t = 0; t < 16; t++) {
            asm volatile("cp.async.wait_group 1;");
            __syncthreads();

            const ulonglong2* sb2 = (const ulonglong2*)sbuf[rb];
            ull SR00 = 0ull, SR01 = 0ull, SR10 = 0ull, SR11 = 0ull;

#pragma unroll
            for (int dp = 0; dp < 8; dp++) {
                ulonglong2 A = sb2[(dp * 3 + 0) * 32 + lane];
                ulonglong2 B = sb2[(dp * 3 + 1) * 32 + lane];
                ulonglong2 C = sb2[(dp * 3 + 2) * 32 + lane];
                float l, h;
                ull u = fma2_(zp0[dp], fma2_(zp0[dp], A.x, B.x), C.x);
                unpk(u, l, h); s0[2 * dp] += ex2f(l); s0[2 * dp + 1] += ex2f(h);
                SR00 = add2_(SR00, u);
                u = fma2_(zp0[dp], fma2_(zp0[dp], A.y, B.y), C.y);
                unpk(u, l, h); s0[2 * dp] += ex2f(l); s0[2 * dp + 1] += ex2f(h);
                SR01 = add2_(SR01, u);
                u = fma2_(zp1[dp], fma2_(zp1[dp], A.x, B.x), C.x);
                unpk(u, l, h); s1[2 * dp] += ex2f(l); s1[2 * dp + 1] += ex2f(h);
                SR10 = add2_(SR10, u);
                u = fma2_(zp1[dp], fma2_(zp1[dp], A.y, B.y), C.y);
                unpk(u, l, h); s1[2 * dp] += ex2f(l); s1[2 * dp + 1] += ex2f(h);
                SR11 = add2_(SR11, u);
            }
            {
                float l, h;
                unpk(SR00, l, h); srow0 += ex2f(l + h);
                unpk(SR01, l, h); srow0 += ex2f(l + h);
                unpk(SR10, l, h); srow1 += ex2f(l + h);
                unpk(SR11, l, h); srow1 += ex2f(l + h);
            }

            // fill tile t+2 into buf[(t+2)%3] == buffer consumed at t-1 (safe:
            // the sync above proves all threads finished compute(t-1)).
            if (t < 14) {
                int fb = rb + 2; if (fb >= 3) fb -= 3;
                unsigned boff = (unsigned)fb * 12288u;
#pragma unroll
                for (int k = 0; k < 3; k++)
                    cpa16(dstb[k] + boff, srcb[k] + (size_t)(t + 2) * 512);
            }
            asm volatile("cp.async.commit_group;");
            if (++rb == 3) rb = 0;
        }

        // ---- post-loop exact corrections: j=0/1 live in half 0, lane 0 ----
        if (half == 0 && lane == 0) {
            const ulonglong2* pk = (const ulonglong2*)g_pk2f;
            float Nf = (float)(*nds);
            float dL0 = lg2f_(2047.0f / Nf);
            float dL1 = lg2f_((Nf - 2047.0f) / Nf);
            float S0_0 = 0.f, S1_0 = 0.f, S0_1 = 0.f, S1_1 = 0.f;
#pragma unroll
            for (int dp = 0; dp < 8; dp++) {
                ulonglong2 A = pk[(dp * 3 + 0) * 1024];
                ulonglong2 B = pk[(dp * 3 + 1) * 1024];
                ulonglong2 C = pk[(dp * 3 + 2) * 1024];
                float l, h;
                ull u0 = fma2_(zp0[dp], fma2_(zp0[dp], A.x, B.x), C.x);
                unpk(u0, l, h); S0_0 += l + h;
                ull u1 = fma2_(zp0[dp], fma2_(zp0[dp], A.y, B.y), C.y);
                unpk(u1, l, h); S1_0 += l + h;
                ull v0 = fma2_(zp1[dp], fma2_(zp1[dp], A.x, B.x), C.x);
                unpk(v0, l, h); S0_1 += l + h;
                ull v1 = fma2_(zp1[dp], fma2_(zp1[dp], A.y, B.y), C.y);
                unpk(v1, l, h); S1_1 += l + h;
            }
            // row-sum: loop applied 16*dL_j; true weight is 1*dL_j(row).
            float c00 = (i0 == Bsz - 2) ? (dL1 - 16.f * dL0) : (-15.f * dL0);
            float c01 = -15.f * dL0;                  // odd rows are never B-2
            float c1  = -15.f * dL1;
            srow0 += (ex2f(c00) - 1.f) * ex2f(S0_0) + (ex2f(c1) - 1.f) * ex2f(S1_0);
            srow1 += (ex2f(c01) - 1.f) * ex2f(S0_1) + (ex2f(c1) - 1.f) * ex2f(S1_1);
            // W[B-2, 0] per-dim override (row B-2 is even -> row i0): recompute u
            if (i0 == Bsz - 2) {
                float wfix = ex2f(dL1 - dL0) - 1.f;
#pragma unroll
                for (int dp = 0; dp < 8; dp++) {
                    ulonglong2 A = pk[(dp * 3 + 0) * 1024];
                    ulonglong2 B = pk[(dp * 3 + 1) * 1024];
                    ulonglong2 C = pk[(dp * 3 + 2) * 1024];
                    float l, h;
                    ull u0 = fma2_(zp0[dp], fma2_(zp0[dp], A.x, B.x), C.x);
                    unpk(u0, l, h);
                    s0[2 * dp] += wfix * ex2f(l);
                    s0[2 * dp + 1] += wfix * ex2f(h);
                }
            }
        }

        // ---- plain-sum butterfly ----
#pragma unroll
        for (int off = 16; off > 0; off >>= 1) {
#pragma unroll
            for (int d = 0; d < 16; d++) {
                s0[d] += __shfl_xor_sync(0xffffffffu, s0[d], off);
                s1[d] += __shfl_xor_sync(0xffffffffu, s1[d], off);
            }
            srow0 += __shfl_xor_sync(0xffffffffu, srow0, off);
            srow1 += __shfl_xor_sync(0xffffffffu, srow1, off);
        }

        // ---- write half partials ----
        if (lane == 0) {
            float4* d0 = (float4*)&g_ph[half][i0 * 20];
            d0[0] = make_float4(s0[0], s0[1], s0[2], s0[3]);
            d0[1] = make_float4(s0[4], s0[5], s0[6], s0[7]);
            d0[2] = make_float4(s0[8], s0[9], s0[10], s0[11]);
            d0[3] = make_float4(s0[12], s0[13], s0[14], s0[15]);
            g_ph[half][i0 * 20 + 16] = srow0;
            float4* d1 = (float4*)&g_ph[half][i1 * 20];
            d1[0] = make_float4(s1[0], s1[1], s1[2], s1[3]);
            d1[1] = make_float4(s1[4], s1[5], s1[6], s1[7]);
            d1[2] = make_float4(s1[8], s1[9], s1[10], s1[11]);
            d1[3] = make_float4(s1[12], s1[13], s1[14], s1[15]);
            g_ph[half][i1 * 20 + 16] = srow1;
        }
        __syncthreads();
        if (tid == 0) {
            __threadfence();
            s_tmp = atomicAdd(&g_rgc[rg], 1u);
        }
        __syncthreads();
        if (s_tmp == 1) {            // second finisher merges this rowgroup
            __threadfence();
            if (lane == 0) {
                const float* o0 = &g_ph[1 - half][i0 * 20];
                float acc = 0.f;
#pragma unroll
                for (int d = 0; d < 16; d++) acc += lg2f_(s0[d] + o0[d]);
                g_comb[i0] = g_arr0[i0]
                           + 3.f * LN2_F * (lg2f_(srow0 + o0[16]) - acc);
                const float* o1 = &g_ph[1 - half][i1 * 20];
                acc = 0.f;
#pragma unroll
                for (int d = 0; d < 16; d++) acc += lg2f_(s1[d] + o1[d]);
                g_comb[i1] = g_arr0[i1]
                           + 3.f * LN2_F * (lg2f_(srow1 + o1[16]) - acc);
            }
        }
    } else {
        // ---------------- recon MAE partial ----------------
        const int rb = blockIdx.x - NPAIR;
        float acc = 0.f;
        const float4* x4 = (const float4*)x;
        const float4* r4 = (const float4*)rec;
        const int n4 = (Bsz * Ff) / 4;
        for (int k = rb * 256 + tid; k < n4; k += NRECON * 256) {
            float4 a = x4[k], b = r4[k];
            acc += fabsf(a.x - b.x) + fabsf(a.y - b.y) + fabsf(a.z - b.z) + fabsf(a.w - b.w);
        }
        sred[tid] = acc;
        __syncthreads();
#pragma unroll
        for (int o = 128; o > 0; o >>= 1) {
            if (tid < o) sred[tid] += sred[tid + o];
            __syncthreads();
        }
        if (tid == 0) g_part[rb] = sred[0];
    }

    // ---------------- last-block final combine ----------------
    __threadfence();
    __syncthreads();
    if (tid == 0) s_tmp = atomicAdd(&g_count, 1u);
    __syncthreads();
    if (s_tmp == NGRID - 1) {
        __threadfence();
        // total = recon_mean + mean(comb) + 45*ln(2047)
        float c = 0.f;
#pragma unroll
        for (int k = 0; k < Bsz / 256; k++)
            c += g_comb[tid + k * 256];
        float rp = (tid < NRECON) ? g_part[tid] : 0.f;

        sred[tid] = c;
        __syncthreads();
#pragma unroll
        for (int o = 128; o > 0; o >>= 1) {
            if (tid < o) sred[tid] += sred[tid + o];
            __syncthreads();
        }
        float ctot = sred[0];
        __syncthreads();
        sred[tid] = rp;
        __syncthreads();
#pragma unroll
        for (int o = 128; o > 0; o >>= 1) {
            if (tid < o) sred[tid] += sred[tid + o];
            __syncthreads();
        }
        if (tid == 0)
            out[0] = sred[0] / (float)(Bsz * Ff) + ctot / (float)Bsz
                   + 45.0f * logf(2047.0f);
    }
}

extern "C" void kernel_launch(void* const* d_in, const int* in_sizes, int n_in,
                              void* d_out, int out_size) {
    const float* x   = (const float*)d_in[0];
    const float* rec = (const float*)d_in[1];
    const float* mu  = (const float*)d_in[2];
    const float* lv  = (const float*)d_in[3];
    const float* z   = (const float*)d_in[4];
    const int*   nds = (const int*)d_in[5];
    float* out = (float*)d_out;

    k_prep<<<136, 256>>>(mu, lv, z, nds);
    k_main<<<NGRID, 256>>>(z, nds, x, rec, out);
}

// round 12
// speedup vs baseline: 1.0855x; 1.0757x over previous
#include <cuda_runtime.h>
#include <math_constants.h>

#define Bsz 2048
#define Dd 16
#define Ff 512
#define LOG2E_F 1.4426950408889634f
#define LN2_F 0.6931471805599453f
#define LOG2PI_F 1.8378770664093453f

#define NPAIR 256            // pairwise blocks: 128 row-groups x 2 j-halves
#define NRECON 40            // recon blocks
#define NGRID (NPAIR + NRECON)   // 296 = exactly one wave (148 SM x 2 CTA)

typedef unsigned long long ull;

// Coefficient store: segment s = dp*3 + type (dp=dim-pair 0..7, type a/b/c),
// each segment is float2[2048] over j: float2[j] = {coef_{2dp}[j], coef_{2dp+1}[j]}
__device__ float g_pk2f[24 * 2048 * 2];   // 393 KB
__device__ float g_arr0[Bsz];             // log q(z|x) - log p(z)
__device__ float g_ph[2][Bsz * 20];       // per-half partials: 16 dim sums + srow (pad 20)
__device__ float g_comb[Bsz];             // arr0 + 3*ln2*(lg2 srow - sum lg2 s_d)
__device__ float g_part[NRECON];          // recon partials
__device__ unsigned g_rgc[128];           // per-rowgroup counters (monotonic, parity)
__device__ unsigned g_count;              // all-blocks counter (monotonic, mod NGRID)
__device__ unsigned g_sync;               // prep grid-barrier counter (monotonic)

__device__ __forceinline__ float ex2f(float x) {
    float y; asm("ex2.approx.ftz.f32 %0, %1;" : "=f"(y) : "f"(x)); return y;
}
__device__ __forceinline__ float lg2f_(float x) {
    float y; asm("lg2.approx.f32 %0, %1;" : "=f"(y) : "f"(x)); return y;
}
__device__ __forceinline__ ull fma2_(ull a, ull b, ull c) {
    ull d; asm("fma.rn.f32x2 %0, %1, %2, %3;" : "=l"(d) : "l"(a), "l"(b), "l"(c)); return d;
}
__device__ __forceinline__ ull add2_(ull a, ull b) {
    ull d; asm("add.rn.f32x2 %0, %1, %2;" : "=l"(d) : "l"(a), "l"(b)); return d;
}
// exp2 of both halves of a packed f32x2, result packed (pack is reg-alloc free)
__device__ __forceinline__ ull ex2p_(ull u) {
    ull r;
    asm("{\n\t.reg .f32 l,h,a,b;\n\t"
        "mov.b64 {l,h}, %1;\n\t"
        "ex2.approx.ftz.f32 a, l;\n\t"
        "ex2.approx.ftz.f32 b, h;\n\t"
        "mov.b64 %0, {a,b};\n\t}" : "=l"(r) : "l"(u));
    return r;
}
__device__ __forceinline__ void unpk(ull v, float& lo, float& hi) {
    asm("mov.b64 {%0, %1}, %2;" : "=f"(lo), "=f"(hi) : "l"(v));
}
__device__ __forceinline__ ull pk2(float lo, float hi) {
    ull v; asm("mov.b64 %0, {%1, %2};" : "=l"(v) : "f"(lo), "f"(hi)); return v;
}
__device__ __forceinline__ void cpa16(unsigned d, const void* s) {
    asm volatile("cp.async.cg.shared.global [%0], [%1], 16;" :: "r"(d), "l"(s));
}

// ---------------------------------------------------------------------------
// Single persistent kernel, one wave (296 blocks x 256 threads, 2 CTAs/SM).
//  Phase 0 (pairwise blocks b<256): prep slice (128 coeffs + 8 arr0 each),
//    then monotonic-counter grid barrier (recon blocks arrive, don't spin).
//  Phase 1: b<256 pairwise (rowgroup x j-half, triple-buffered cp.async);
//           b>=256 recon MAE partials.
//  Last block overall (mod-NGRID counter) does the final combine -> out[0].
// All counters are monotonic => graph-replay safe with no reset kernel.
// ---------------------------------------------------------------------------
__global__ void __launch_bounds__(256, 2) k_all(const float* __restrict__ mu,
                                                const float* __restrict__ lv,
                                                const float* __restrict__ z,
                                                const int* __restrict__ nds,
                                                const float* __restrict__ x,
                                                const float* __restrict__ rec,
                                                float* __restrict__ out) {
    __shared__ float4 sbuf[3][768];               // 3 x 12 KB tiles
    __shared__ float sred[256];
    __shared__ unsigned s_tmp;
    const int tid = threadIdx.x;
    const int lane = tid & 31;
    const int b = blockIdx.x;

    if (b < NPAIR) {
        // ================= phase 0: prep slice =================
        if (tid < 128) {
            int idx = b * 128 + tid;              // 256*128 = 32768 = Bsz*Dd
            int j = idx >> 4, d = idx & 15;
            float m = mu[idx], v = lv[idx];
            float a = -0.5f * LOG2E_F * ex2f(-v * LOG2E_F);
            float off = -0.5f * LOG2E_F * (v + LOG2PI_F);
            float bb = -2.0f * a * m;
            float c = fmaf(a * m, m, off);
            if (j < 2) {
                float Nf = (float)(*nds);
                float dL0 = lg2f_(2047.0f / Nf);
                float dL1 = lg2f_((Nf - 2047.0f) / Nf);
                c += (j == 0) ? dL0 : dL1;
            }
            int dp = d >> 1, h = d & 1;
            int e = j * 2 + h;
            g_pk2f[(dp * 3 + 0) * 4096 + e] = a;
            g_pk2f[(dp * 3 + 1) * 4096 + e] = bb;
            g_pk2f[(dp * 3 + 2) * 4096 + e] = c;
        } else if (tid < 136) {
            int i = b * 8 + (tid - 128);          // 256*8 = 2048
            float acc = 0.f, sz2 = 0.f;
#pragma unroll
            for (int d = 0; d < Dd; d++) {
                float zd = z[i * Dd + d];
                float md = mu[i * Dd + d];
                float vd = lv[i * Dd + d];
                float t = zd - md;
                acc += -0.5f * (t * t * ex2f(-vd * LOG2E_F) + vd + LOG2PI_F);
                sz2 = fmaf(zd, zd, sz2);
            }
            float lprior = -0.5f * (sz2 * 0.36787944117144233f + 16.0f * (1.0f + LOG2PI_F));
            g_arr0[i] = acc - lprior;
        }
        __threadfence();
        __syncthreads();
        if (tid == 0) {
            unsigned old = atomicAdd(&g_sync, 1u);
            unsigned target = (old / NGRID + 1u) * NGRID;
            while (*(volatile unsigned*)&g_sync < target) { }
        }
        __syncthreads();
        __threadfence();

        // ================= phase 1: pairwise =================
        const int half = b >> 7;                  // 0 or 1 (j-half)
        const int rg = b & 127;                   // row-group (16 rows)
        const int w = tid >> 5;                   // 0..7
        const int i0 = rg * 16 + 2 * w, i1 = i0 + 1;

        ull zp0[8], zp1[8];
        {
            const float4* zq = (const float4*)(z + (size_t)i0 * Dd);
#pragma unroll
            for (int k = 0; k < 4; k++) {
                float4 v = zq[k];
                zp0[2 * k] = pk2(v.x, v.y); zp0[2 * k + 1] = pk2(v.z, v.w);
            }
            const float4* zq1 = (const float4*)(z + (size_t)i1 * Dd);
#pragma unroll
            for (int k = 0; k < 4; k++) {
                float4 v = zq1[k];
                zp1[2 * k] = pk2(v.x, v.y); zp1[2 * k + 1] = pk2(v.z, v.w);
            }
        }

        ull s20[8], s21[8];                       // packed per-dim sums
        float srow0 = 0.f, srow1 = 0.f;
#pragma unroll
        for (int dp = 0; dp < 8; dp++) { s20[dp] = 0ull; s21[dp] = 0ull; }

        // cp.async bases: chunk k covers element e=tid+k*256 -> seg s=e>>5, q=e&31
        const char* srcb[3];
        unsigned dstb[3];
        {
            unsigned sm0 = (unsigned)__cvta_generic_to_shared(&sbuf[0][0]);
#pragma unroll
            for (int k = 0; k < 3; k++) {
                int e = tid + k * 256; int s = e >> 5, q = e & 31;
                srcb[k] = (const char*)g_pk2f + ((size_t)(s * 1024 + q)) * 16
                        + (size_t)half * 8192;
                dstb[k] = sm0 + (unsigned)(s * 32 + q) * 16u;
            }
        }
        // prologue: stage tiles 0 and 1
#pragma unroll
        for (int k = 0; k < 3; k++) cpa16(dstb[k], srcb[k]);
        asm volatile("cp.async.commit_group;");
#pragma unroll
        for (int k = 0; k < 3; k++) cpa16(dstb[k] + 12288u, srcb[k] + 512);
        asm volatile("cp.async.commit_group;");

        int rb = 0;   // t % 3
#pragma unroll 1
        for (int t = 0; t < 16; t++) {
            asm volatile("cp.async.wait_group 1;");
            __syncthreads();

            const ulonglong2* sb2 = (const ulonglong2*)sbuf[rb];
            ull SR00 = 0ull, SR01 = 0ull, SR10 = 0ull, SR11 = 0ull;

#pragma unroll
            for (int dp = 0; dp < 8; dp++) {
                ulonglong2 A = sb2[(dp * 3 + 0) * 32 + lane];
                ulonglong2 B = sb2[(dp * 3 + 1) * 32 + lane];
                ulonglong2 C = sb2[(dp * 3 + 2) * 32 + lane];
                ull u = fma2_(zp0[dp], fma2_(zp0[dp], A.x, B.x), C.x);
                s20[dp] = add2_(s20[dp], ex2p_(u));
                SR00 = add2_(SR00, u);
                u = fma2_(zp0[dp], fma2_(zp0[dp], A.y, B.y), C.y);
                s20[dp] = add2_(s20[dp], ex2p_(u));
                SR01 = add2_(SR01, u);
                u = fma2_(zp1[dp], fma2_(zp1[dp], A.x, B.x), C.x);
                s21[dp] = add2_(s21[dp], ex2p_(u));
                SR10 = add2_(SR10, u);
                u = fma2_(zp1[dp], fma2_(zp1[dp], A.y, B.y), C.y);
                s21[dp] = add2_(s21[dp], ex2p_(u));
                SR11 = add2_(SR11, u);
            }
            {
                float l, h;
                unpk(SR00, l, h); srow0 += ex2f(l + h);
                unpk(SR01, l, h); srow0 += ex2f(l + h);
                unpk(SR10, l, h); srow1 += ex2f(l + h);
                unpk(SR11, l, h); srow1 += ex2f(l + h);
            }

            // fill tile t+2 into buf[(t+2)%3] == buffer consumed at t-1 (safe:
            // the sync above proves all threads finished compute(t-1)).
            if (t < 14) {
                int fb = rb + 2; if (fb >= 3) fb -= 3;
                unsigned boff = (unsigned)fb * 12288u;
#pragma unroll
                for (int k = 0; k < 3; k++)
                    cpa16(dstb[k] + boff, srcb[k] + (size_t)(t + 2) * 512);
            }
            asm volatile("cp.async.commit_group;");
            if (++rb == 3) rb = 0;
        }

        // unpack packed accumulators
        float s0[16], s1[16];
#pragma unroll
        for (int dp = 0; dp < 8; dp++) {
            unpk(s20[dp], s0[2 * dp], s0[2 * dp + 1]);
            unpk(s21[dp], s1[2 * dp], s1[2 * dp + 1]);
        }

        // ---- post-loop exact corrections: j=0/1 live in half 0, lane 0 ----
        if (half == 0 && lane == 0) {
            const ulonglong2* pk = (const ulonglong2*)g_pk2f;
            float Nf = (float)(*nds);
            float dL0 = lg2f_(2047.0f / Nf);
            float dL1 = lg2f_((Nf - 2047.0f) / Nf);
            float S0_0 = 0.f, S1_0 = 0.f, S0_1 = 0.f, S1_1 = 0.f;
#pragma unroll
            for (int dp = 0; dp < 8; dp++) {
                ulonglong2 A = pk[(dp * 3 + 0) * 1024];
                ulonglong2 B = pk[(dp * 3 + 1) * 1024];
                ulonglong2 C = pk[(dp * 3 + 2) * 1024];
                float l, h;
                ull u0 = fma2_(zp0[dp], fma2_(zp0[dp], A.x, B.x), C.x);
                unpk(u0, l, h); S0_0 += l + h;
                ull u1 = fma2_(zp0[dp], fma2_(zp0[dp], A.y, B.y), C.y);
                unpk(u1, l, h); S1_0 += l + h;
                ull v0 = fma2_(zp1[dp], fma2_(zp1[dp], A.x, B.x), C.x);
                unpk(v0, l, h); S0_1 += l + h;
                ull v1 = fma2_(zp1[dp], fma2_(zp1[dp], A.y, B.y), C.y);
                unpk(v1, l, h); S1_1 += l + h;
            }
            // row-sum: loop applied 16*dL_j; true weight is 1*dL_j(row).
            float c00 = (i0 == Bsz - 2) ? (dL1 - 16.f * dL0) : (-15.f * dL0);
            float c01 = -15.f * dL0;                  // odd rows are never B-2
            float c1  = -15.f * dL1;
            srow0 += (ex2f(c00) - 1.f) * ex2f(S0_0) + (ex2f(c1) - 1.f) * ex2f(S1_0);
            srow1 += (ex2f(c01) - 1.f) * ex2f(S0_1) + (ex2f(c1) - 1.f) * ex2f(S1_1);
            // W[B-2, 0] per-dim override (row B-2 is even -> row i0): recompute u
            if (i0 == Bsz - 2) {
                float wfix = ex2f(dL1 - dL0) - 1.f;
#pragma unroll
                for (int dp = 0; dp < 8; dp++) {
                    ulonglong2 A = pk[(dp * 3 + 0) * 1024];
                    ulonglong2 B = pk[(dp * 3 + 1) * 1024];
                    ulonglong2 C = pk[(dp * 3 + 2) * 1024];
                    float l, h;
                    ull u0 = fma2_(zp0[dp], fma2_(zp0[dp], A.x, B.x), C.x);
                    unpk(u0, l, h);
                    s0[2 * dp] += wfix * ex2f(l);
                    s0[2 * dp + 1] += wfix * ex2f(h);
                }
            }
        }

        // ---- plain-sum butterfly ----
#pragma unroll
        for (int off = 16; off > 0; off >>= 1) {
#pragma unroll
            for (int d = 0; d < 16; d++) {
                s0[d] += __shfl_xor_sync(0xffffffffu, s0[d], off);
                s1[d] += __shfl_xor_sync(0xffffffffu, s1[d], off);
            }
            srow0 += __shfl_xor_sync(0xffffffffu, srow0, off);
            srow1 += __shfl_xor_sync(0xffffffffu, srow1, off);
        }

        // ---- write half partials ----
        if (lane == 0) {
            float4* d0 = (float4*)&g_ph[half][i0 * 20];
            d0[0] = make_float4(s0[0], s0[1], s0[2], s0[3]);
            d0[1] = make_float4(s0[4], s0[5], s0[6], s0[7]);
            d0[2] = make_float4(s0[8], s0[9], s0[10], s0[11]);
            d0[3] = make_float4(s0[12], s0[13], s0[14], s0[15]);
            g_ph[half][i0 * 20 + 16] = srow0;
            float4* d1 = (float4*)&g_ph[half][i1 * 20];
            d1[0] = make_float4(s1[0], s1[1], s1[2], s1[3]);
            d1[1] = make_float4(s1[4], s1[5], s1[6], s1[7]);
            d1[2] = make_float4(s1[8], s1[9], s1[10], s1[11]);
            d1[3] = make_float4(s1[12], s1[13], s1[14], s1[15]);
            g_ph[half][i1 * 20 + 16] = srow1;
        }
        __syncthreads();
        if (tid == 0) {
            __threadfence();
            s_tmp = atomicAdd(&g_rgc[rg], 1u);
        }
        __syncthreads();
        if (s_tmp & 1u) {            // second finisher (this replay) merges
            __threadfence();
            if (lane == 0) {
                const float* o0 = &g_ph[1 - half][i0 * 20];
                float acc = 0.f;
#pragma unroll
                for (int d = 0; d < 16; d++) acc += lg2f_(s0[d] + o0[d]);
                g_comb[i0] = g_arr0[i0]
                           + 3.f * LN2_F * (lg2f_(srow0 + o0[16]) - acc);
                const float* o1 = &g_ph[1 - half][i1 * 20];
                acc = 0.f;
#pragma unroll
                for (int d = 0; d < 16; d++) acc += lg2f_(s1[d] + o1[d]);
                g_comb[i1] = g_arr0[i1]
                           + 3.f * LN2_F * (lg2f_(srow1 + o1[16]) - acc);
            }
        }
    } else {
        // ---------------- recon MAE partial (arrive, no spin) ----------------
        if (tid == 0) atomicAdd(&g_sync, 1u);
        const int rbk = b - NPAIR;
        float acc = 0.f;
        const float4* x4 = (const float4*)x;
        const float4* r4 = (const float4*)rec;
        const int n4 = (Bsz * Ff) / 4;
        for (int k = rbk * 256 + tid; k < n4; k += NRECON * 256) {
            float4 a = x4[k], bb = r4[k];
            acc += fabsf(a.x - bb.x) + fabsf(a.y - bb.y)
                 + fabsf(a.z - bb.z) + fabsf(a.w - bb.w);
        }
        sred[tid] = acc;
        __syncthreads();
#pragma unroll
        for (int o = 128; o > 0; o >>= 1) {
            if (tid < o) sred[tid] += sred[tid + o];
            __syncthreads();
        }
        if (tid == 0) g_part[rbk] = sred[0];
    }

    // ---------------- last-block final combine ----------------
    __threadfence();
    __syncthreads();
    if (tid == 0) s_tmp = atomicAdd(&g_count, 1u);
    __syncthreads();
    if (s_tmp % NGRID == NGRID - 1) {
        __threadfence();
        // total = recon_mean + mean(comb) + 45*ln(2047)
        float c = 0.f;
#pragma unroll
        for (int k = 0; k < Bsz / 256; k++)
            c += g_comb[tid + k * 256];
        float rp = (tid < NRECON) ? g_part[tid] : 0.f;

        sred[tid] = c;
        __syncthreads();
#pragma unroll
        for (int o = 128; o > 0; o >>= 1) {
            if (tid < o) sred[tid] += sred[tid + o];
            __syncthreads();
        }
        float ctot = sred[0];
        __syncthreads();
        sred[tid] = rp;
        __syncthreads();
#pragma unroll
        for (int o = 128; o > 0; o >>= 1) {
            if (tid < o) sred[tid] += sred[tid + o];
            __syncthreads();
        }
        if (tid == 0)
            out[0] = sred[0] / (float)(Bsz * Ff) + ctot / (float)Bsz
                   + 45.0f * logf(2047.0f);
    }
}

extern "C" void kernel_launch(void* const* d_in, const int* in_sizes, int n_in,
                              void* d_out, int out_size) {
    const float* x   = (const float*)d_in[0];
    const float* rec = (const float*)d_in[1];
    const float* mu  = (const float*)d_in[2];
    const float* lv  = (const float*)d_in[3];
    const float* z   = (const float*)d_in[4];
    const int*   nds = (const int*)d_in[5];
    float* out = (float*)d_out;

    k_all<<<NGRID, 256>>>(mu, lv, z, nds, x, rec, out);
}